// round 2
// baseline (speedup 1.0000x reference)
#include <cuda_runtime.h>
#include <math.h>

#define BB 4
#define SS 1024
#define DD 1024
#define TT (BB*SS)           // 4096 tokens
#define HH 16
#define KVHH 4
#define HDD 64
#define EE 8
#define FFF 2816
#define CCOMP 256
#define NSLOT (TT*2)         // 8192 (token, expert) slots

// ---------------- scratch (static device globals; no runtime alloc) ----------
__device__ float g_X[TT*DD];            // rmsnorm1 output
__device__ float g_Q[TT*DD];
__device__ float g_K[TT*KVHH*HDD];
__device__ float g_V[TT*KVHH*HDD];
__device__ float g_attn[TT*DD];         // attention context (pre-WO)
__device__ float g_attnout[TT*DD];      // after WO
__device__ float g_h2[TT*DD];           // rmsnorm2 output
__device__ float g_act[NSLOT*FFF];      // silu(h1)*h3 per slot
__device__ float g_part[NSLOT*DD];      // weighted expert outputs per slot
__device__ int   g_tok[NSLOT];          // slot -> token
__device__ float g_slotw[NSLOT];        // slot -> gate weight
__device__ int   g_tokslot[TT*2];       // token,k -> slot
__device__ int   g_te[TT*2];            // token,k -> expert
__device__ float g_tw[TT*2];            // token,k -> weight
__device__ int   g_cnt[EE];
__device__ int   g_off[EE+1];
__device__ int   g_cur[EE];

// ---------------- rmsnorm ----------------------------------------------------
__global__ __launch_bounds__(256) void rmsnorm_kernel(
    const float* __restrict__ x, const float* __restrict__ w, float* __restrict__ out) {
  int row = blockIdx.x;
  const float* xr = x + (size_t)row * DD;
  float ss = 0.f;
  for (int i = threadIdx.x; i < DD; i += 256) { float v = xr[i]; ss += v * v; }
  __shared__ float red[8];
#pragma unroll
  for (int o = 16; o; o >>= 1) ss += __shfl_xor_sync(0xffffffffu, ss, o);
  if ((threadIdx.x & 31) == 0) red[threadIdx.x >> 5] = ss;
  __syncthreads();
  if (threadIdx.x < 8) {
    float v = red[threadIdx.x];
#pragma unroll
    for (int o = 4; o; o >>= 1) v += __shfl_xor_sync(0xffu, v, o);
    if (threadIdx.x == 0) red[0] = rsqrtf(v / (float)DD + 1e-6f);
  }
  __syncthreads();
  float r = red[0];
  for (int i = threadIdx.x; i < DD; i += 256) out[(size_t)row * DD + i] = w[i] * (xr[i] * r);
}

// ---------------- generic SGEMM: C[M,N] = A[M,K] @ B[K,N] (+bias) ------------
// grid = (N/64, M/64); M,N multiples of 64; K multiple of 16.
__global__ __launch_bounds__(256) void sgemm_kernel(
    const float* __restrict__ A, const float* __restrict__ Bw,
    const float* __restrict__ bias, float* __restrict__ C, int N, int K) {
  __shared__ float As[16][64];
  __shared__ float Bs[16][64];
  int tid = threadIdx.x;
  int tx = tid & 15, ty = tid >> 4;
  int rowBase = blockIdx.y * 64;
  int colBase = blockIdx.x * 64;
  int aRow = tid >> 2, aCol = (tid & 3) * 4;
  int bRow = tid >> 4, bCol = (tid & 15) * 4;
  const float* Ap = A + (size_t)(rowBase + aRow) * K + aCol;
  const float* Bp = Bw + (size_t)bRow * N + colBase + bCol;
  float acc[4][4] = {};
  for (int k0 = 0; k0 < K; k0 += 16) {
    float4 av = *(const float4*)(Ap + k0);
    As[aCol][aRow] = av.x; As[aCol+1][aRow] = av.y; As[aCol+2][aRow] = av.z; As[aCol+3][aRow] = av.w;
    *(float4*)&Bs[bRow][bCol] = *(const float4*)(Bp + (size_t)k0 * N);
    __syncthreads();
#pragma unroll
    for (int k = 0; k < 16; k++) {
      float4 a4 = *(const float4*)&As[k][ty*4];
      float4 b4 = *(const float4*)&Bs[k][tx*4];
      float ar[4] = {a4.x, a4.y, a4.z, a4.w};
      float br[4] = {b4.x, b4.y, b4.z, b4.w};
#pragma unroll
      for (int i = 0; i < 4; i++)
#pragma unroll
        for (int j = 0; j < 4; j++) acc[i][j] += ar[i] * br[j];
    }
    __syncthreads();
  }
#pragma unroll
  for (int i = 0; i < 4; i++) {
    int r = rowBase + ty*4 + i;
#pragma unroll
    for (int j = 0; j < 4; j++) {
      int c = colBase + tx*4 + j;
      float v = acc[i][j];
      if (bias) v += bias[c];
      C[(size_t)r * N + c] = v;
    }
  }
}

// ---------------- attention (flash-lite, no mask) ----------------------------
// grid (8, 16, 4), 128 threads; thread = one query row; online softmax.
__global__ __launch_bounds__(128) void attn_kernel() {
  int q = blockIdx.x * 128 + threadIdx.x;   // seq pos
  int h = blockIdx.y;
  int b = blockIdx.z;
  int t = b * SS + q;
  int kv = h / (HH / KVHH);
  const float* qp = g_Q + (size_t)t * DD + h * HDD;
  float qr[HDD];
#pragma unroll
  for (int i = 0; i < HDD; i++) qr[i] = qp[i] * 0.125f;  // 1/sqrt(64)
  float acc[HDD] = {};
  float m = -1e30f, l = 0.f;
  __shared__ float Ks[32][HDD];
  __shared__ float Vs[32][HDD];
  int lr = threadIdx.x >> 2;
  int lc = (threadIdx.x & 3) * 16;
  for (int kt = 0; kt < SS; kt += 32) {
    const float* kp = g_K + (size_t)(b*SS + kt + lr) * (KVHH*HDD) + kv*HDD + lc;
    const float* vp = g_V + (size_t)(b*SS + kt + lr) * (KVHH*HDD) + kv*HDD + lc;
#pragma unroll
    for (int i = 0; i < 4; i++) {
      *(float4*)&Ks[lr][lc + i*4] = *(const float4*)(kp + i*4);
      *(float4*)&Vs[lr][lc + i*4] = *(const float4*)(vp + i*4);
    }
    __syncthreads();
    float sc[32];
#pragma unroll
    for (int j = 0; j < 32; j++) {
      float s = 0.f;
#pragma unroll
      for (int i = 0; i < HDD/4; i++) {
        float4 k4 = *(const float4*)&Ks[j][i*4];
        s += qr[i*4]*k4.x + qr[i*4+1]*k4.y + qr[i*4+2]*k4.z + qr[i*4+3]*k4.w;
      }
      sc[j] = s;
    }
    float mt = m;
#pragma unroll
    for (int j = 0; j < 32; j++) mt = fmaxf(mt, sc[j]);
    float corr = __expf(m - mt);
    m = mt;
    l *= corr;
#pragma unroll
    for (int i = 0; i < HDD; i++) acc[i] *= corr;
#pragma unroll
    for (int j = 0; j < 32; j++) {
      float p = __expf(sc[j] - m);
      l += p;
#pragma unroll
      for (int i = 0; i < HDD/4; i++) {
        float4 v4 = *(const float4*)&Vs[j][i*4];
        acc[i*4]   += p * v4.x;
        acc[i*4+1] += p * v4.y;
        acc[i*4+2] += p * v4.z;
        acc[i*4+3] += p * v4.w;
      }
    }
    __syncthreads();
  }
  float inv = 1.f / l;
  float* op = g_attn + (size_t)t * DD + h * HDD;
#pragma unroll
  for (int i = 0; i < HDD; i++) op[i] = acc[i] * inv;
}

// ---------------- mix: mixed = [attnout, prev] @ mix_w + b; h = hidden+mixed -
__global__ __launch_bounds__(256) void mix_kernel(
    const float* __restrict__ hidden, const float* __restrict__ prev,
    const float* __restrict__ mixw, const float* __restrict__ mixb,
    float* __restrict__ out_mixed, float* __restrict__ out_h) {
  __shared__ float As[16][64];
  __shared__ float Bs[16][64];
  int tid = threadIdx.x;
  int tx = tid & 15, ty = tid >> 4;
  int rowBase = blockIdx.y * 64;
  int colBase = blockIdx.x * 64;
  int aRow = tid >> 2, aCol = (tid & 3) * 4;
  int bRow = tid >> 4, bCol = (tid & 15) * 4;
  float acc[4][4] = {};
  for (int k0 = 0; k0 < 2*DD; k0 += 16) {
    const float* Ap = (k0 < DD)
        ? g_attnout + (size_t)(rowBase + aRow) * DD + k0 + aCol
        : prev      + (size_t)(rowBase + aRow) * DD + (k0 - DD) + aCol;
    float4 av = *(const float4*)Ap;
    As[aCol][aRow] = av.x; As[aCol+1][aRow] = av.y; As[aCol+2][aRow] = av.z; As[aCol+3][aRow] = av.w;
    *(float4*)&Bs[bRow][bCol] = *(const float4*)(mixw + (size_t)(k0 + bRow) * DD + colBase + bCol);
    __syncthreads();
#pragma unroll
    for (int k = 0; k < 16; k++) {
      float4 a4 = *(const float4*)&As[k][ty*4];
      float4 b4 = *(const float4*)&Bs[k][tx*4];
      float ar[4] = {a4.x, a4.y, a4.z, a4.w};
      float br[4] = {b4.x, b4.y, b4.z, b4.w};
#pragma unroll
      for (int i = 0; i < 4; i++)
#pragma unroll
        for (int j = 0; j < 4; j++) acc[i][j] += ar[i] * br[j];
    }
    __syncthreads();
  }
#pragma unroll
  for (int i = 0; i < 4; i++) {
    int r = rowBase + ty*4 + i;
#pragma unroll
    for (int j = 0; j < 4; j++) {
      int c = colBase + tx*4 + j;
      float mval = acc[i][j] + mixb[c];
      out_mixed[(size_t)r * DD + c] = mval;
      out_h[(size_t)r * DD + c] = hidden[(size_t)r * DD + c] + mval;
    }
  }
}

// ---------------- MoE routing ------------------------------------------------
__global__ void zero_kernel() { if (threadIdx.x < EE) g_cnt[threadIdx.x] = 0; }

__global__ __launch_bounds__(256) void gate_kernel(
    const float* __restrict__ gw) {
  int warp = (blockIdx.x * 256 + threadIdx.x) >> 5;
  int lane = threadIdx.x & 31;
  if (warp >= TT) return;
  const float* x = g_h2 + (size_t)warp * DD;
  float acc[EE] = {};
  for (int k = lane; k < DD; k += 32) {
    float xv = x[k];
    const float* g = gw + (size_t)k * EE;
#pragma unroll
    for (int e = 0; e < EE; e++) acc[e] += xv * g[e];
  }
#pragma unroll
  for (int e = 0; e < EE; e++)
#pragma unroll
    for (int o = 16; o; o >>= 1) acc[e] += __shfl_xor_sync(0xffffffffu, acc[e], o);
  if (lane == 0) {
    float mx = acc[0];
#pragma unroll
    for (int e = 1; e < EE; e++) mx = fmaxf(mx, acc[e]);
    float p[EE];
#pragma unroll
    for (int e = 0; e < EE; e++) p[e] = __expf(acc[e] - mx);
    int i0 = 0;
#pragma unroll
    for (int e = 1; e < EE; e++) if (p[e] > p[i0]) i0 = e;
    int i1 = (i0 == 0) ? 1 : 0;
#pragma unroll
    for (int e = 0; e < EE; e++) if (e != i0 && p[e] > p[i1]) i1 = e;
    float w0 = p[i0], w1 = p[i1];
    float inv = 1.f / (w0 + w1);           // softmax denom cancels under top-2 renorm
    w0 *= inv; w1 *= inv;
    g_te[warp*2] = i0; g_te[warp*2+1] = i1;
    g_tw[warp*2] = w0; g_tw[warp*2+1] = w1;
    atomicAdd(&g_cnt[i0], 1);
    atomicAdd(&g_cnt[i1], 1);
  }
}

__global__ void scan_kernel() {
  if (threadIdx.x == 0) {
    int o = 0;
    for (int e = 0; e < EE; e++) { g_off[e] = o; o += g_cnt[e]; g_cur[e] = 0; }
    g_off[EE] = o;
  }
}

__global__ __launch_bounds__(256) void scatter_kernel() {
  int t = blockIdx.x * 256 + threadIdx.x;
  if (t >= TT) return;
#pragma unroll
  for (int k = 0; k < 2; k++) {
    int e = g_te[t*2+k];
    int pos = atomicAdd(&g_cur[e], 1);
    int slot = g_off[e] + pos;
    g_tok[slot] = t;
    g_slotw[slot] = g_tw[t*2+k];
    g_tokslot[t*2+k] = slot;
  }
}

// ---------------- MoE up: act = silu(X@w1[e]) * (X@w3[e]), gathered rows -----
// grid (44, 64, 8)
__global__ __launch_bounds__(256) void moe_up_kernel(
    const float* __restrict__ w1, const float* __restrict__ w3) {
  int e = blockIdx.z;
  int base = g_off[e];
  int cnt = g_off[e+1] - base;
  int rowBase = blockIdx.y * 64;
  if (rowBase >= cnt) return;
  int colBase = blockIdx.x * 64;
  __shared__ float As[16][64];
  __shared__ float B1s[16][64];
  __shared__ float B3s[16][64];
  int tid = threadIdx.x;
  int tx = tid & 15, ty = tid >> 4;
  int aRow = tid >> 2, aCol = (tid & 3) * 4;
  int bRow = tid >> 4, bCol = (tid & 15) * 4;
  int r = rowBase + aRow;
  int tok = g_tok[base + ((r < cnt) ? r : 0)];
  const float* Ap  = g_h2 + (size_t)tok * DD + aCol;
  const float* B1p = w1 + (size_t)e * DD * FFF + (size_t)bRow * FFF + colBase + bCol;
  const float* B3p = w3 + (size_t)e * DD * FFF + (size_t)bRow * FFF + colBase + bCol;
  float acc1[4][4] = {}, acc3[4][4] = {};
  for (int k0 = 0; k0 < DD; k0 += 16) {
    float4 av = *(const float4*)(Ap + k0);
    As[aCol][aRow] = av.x; As[aCol+1][aRow] = av.y; As[aCol+2][aRow] = av.z; As[aCol+3][aRow] = av.w;
    *(float4*)&B1s[bRow][bCol] = *(const float4*)(B1p + (size_t)k0 * FFF);
    *(float4*)&B3s[bRow][bCol] = *(const float4*)(B3p + (size_t)k0 * FFF);
    __syncthreads();
#pragma unroll
    for (int k = 0; k < 16; k++) {
      float4 a4 = *(const float4*)&As[k][ty*4];
      float4 b1 = *(const float4*)&B1s[k][tx*4];
      float4 b3 = *(const float4*)&B3s[k][tx*4];
      float ar[4]  = {a4.x, a4.y, a4.z, a4.w};
      float b1r[4] = {b1.x, b1.y, b1.z, b1.w};
      float b3r[4] = {b3.x, b3.y, b3.z, b3.w};
#pragma unroll
      for (int i = 0; i < 4; i++)
#pragma unroll
        for (int j = 0; j < 4; j++) {
          acc1[i][j] += ar[i] * b1r[j];
          acc3[i][j] += ar[i] * b3r[j];
        }
    }
    __syncthreads();
  }
#pragma unroll
  for (int i = 0; i < 4; i++) {
    int rr = rowBase + ty*4 + i;
    if (rr < cnt) {
      float* dst = g_act + (size_t)(base + rr) * FFF + colBase + tx*4;
#pragma unroll
      for (int j = 0; j < 4; j++) {
        float h1 = acc1[i][j], h3 = acc3[i][j];
        dst[j] = h1 / (1.f + __expf(-h1)) * h3;
      }
    }
  }
}

// ---------------- MoE down: part[slot] = w_slot * (act[slot] @ w2[e]) --------
// grid (16, 64, 8)
__global__ __launch_bounds__(256) void moe_down_kernel(const float* __restrict__ w2) {
  int e = blockIdx.z;
  int base = g_off[e];
  int cnt = g_off[e+1] - base;
  int rowBase = blockIdx.y * 64;
  if (rowBase >= cnt) return;
  int colBase = blockIdx.x * 64;
  __shared__ float As[16][64];
  __shared__ float Bs[16][64];
  int tid = threadIdx.x;
  int tx = tid & 15, ty = tid >> 4;
  int aRow = tid >> 2, aCol = (tid & 3) * 4;
  int bRow = tid >> 4, bCol = (tid & 15) * 4;
  int r = rowBase + aRow;
  int ar_slot = base + ((r < cnt) ? r : 0);
  const float* Ap = g_act + (size_t)ar_slot * FFF + aCol;
  const float* Bp = w2 + (size_t)e * FFF * DD + (size_t)bRow * DD + colBase + bCol;
  float acc[4][4] = {};
  for (int k0 = 0; k0 < FFF; k0 += 16) {
    float4 av = *(const float4*)(Ap + k0);
    As[aCol][aRow] = av.x; As[aCol+1][aRow] = av.y; As[aCol+2][aRow] = av.z; As[aCol+3][aRow] = av.w;
    *(float4*)&Bs[bRow][bCol] = *(const float4*)(Bp + (size_t)k0 * DD);
    __syncthreads();
#pragma unroll
    for (int k = 0; k < 16; k++) {
      float4 a4 = *(const float4*)&As[k][ty*4];
      float4 b4 = *(const float4*)&Bs[k][tx*4];
      float ar[4] = {a4.x, a4.y, a4.z, a4.w};
      float br[4] = {b4.x, b4.y, b4.z, b4.w};
#pragma unroll
      for (int i = 0; i < 4; i++)
#pragma unroll
        for (int j = 0; j < 4; j++) acc[i][j] += ar[i] * br[j];
    }
    __syncthreads();
  }
#pragma unroll
  for (int i = 0; i < 4; i++) {
    int rr = rowBase + ty*4 + i;
    if (rr < cnt) {
      float wgt = g_slotw[base + rr];
      float* dst = g_part + (size_t)(base + rr) * DD + colBase + tx*4;
#pragma unroll
      for (int j = 0; j < 4; j++) dst[j] = wgt * acc[i][j];
    }
  }
}

// ---------------- combine: h += part[slot0] + part[slot1] --------------------
__global__ __launch_bounds__(256) void combine_kernel(float* __restrict__ outh) {
  int t = blockIdx.x;
  int s0 = g_tokslot[t*2], s1 = g_tokslot[t*2+1];
  int i = threadIdx.x * 4;
  float4 h  = *(float4*)(outh + (size_t)t * DD + i);
  float4 p0 = *(const float4*)(g_part + (size_t)s0 * DD + i);
  float4 p1 = *(const float4*)(g_part + (size_t)s1 * DD + i);
  h.x += p0.x + p1.x; h.y += p0.y + p1.y; h.z += p0.z + p1.z; h.w += p0.w + p1.w;
  *(float4*)(outh + (size_t)t * DD + i) = h;
}

// ---------------- launcher ---------------------------------------------------
extern "C" void kernel_launch(void* const* d_in, const int* in_sizes, int n_in,
                              void* d_out, int out_size) {
  const float* hidden = (const float*)d_in[0];
  // d_in[1] = position_ids (int64) — unused
  const float* prev   = (const float*)d_in[2];
  const float* wq     = (const float*)d_in[3];
  const float* wk     = (const float*)d_in[4];
  const float* wv     = (const float*)d_in[5];
  const float* wo     = (const float*)d_in[6];
  const float* mixw   = (const float*)d_in[7];
  const float* mixb   = (const float*)d_in[8];
  const float* gatew  = (const float*)d_in[9];
  const float* w1     = (const float*)d_in[10];
  const float* w2     = (const float*)d_in[11];
  const float* w3     = (const float*)d_in[12];
  const float* ln1    = (const float*)d_in[13];
  const float* ln2    = (const float*)d_in[14];
  const float* compw  = (const float*)d_in[15];
  const float* compb  = (const float*)d_in[16];

  float* out_h     = (float*)d_out;
  float* out_mixed = out_h + (size_t)TT * DD;
  float* out_comp  = out_mixed + (size_t)TT * DD;

  void *pX, *pQ, *pK, *pV, *pAttn, *pAttnOut, *pH2;
  cudaGetSymbolAddress(&pX, g_X);
  cudaGetSymbolAddress(&pQ, g_Q);
  cudaGetSymbolAddress(&pK, g_K);
  cudaGetSymbolAddress(&pV, g_V);
  cudaGetSymbolAddress(&pAttn, g_attn);
  cudaGetSymbolAddress(&pAttnOut, g_attnout);
  cudaGetSymbolAddress(&pH2, g_h2);
  float* X = (float*)pX; float* Q = (float*)pQ; float* K = (float*)pK;
  float* V = (float*)pV; float* ATT = (float*)pAttn; float* AO = (float*)pAttnOut;
  float* H2 = (float*)pH2;

  // 1. x = rmsnorm(hidden, ln1)
  rmsnorm_kernel<<<TT, 256>>>(hidden, ln1, X);
  // 2. QKV projections
  sgemm_kernel<<<dim3(DD/64, TT/64), 256>>>(X, wq, nullptr, Q, DD, DD);
  sgemm_kernel<<<dim3((KVHH*HDD)/64, TT/64), 256>>>(X, wk, nullptr, K, KVHH*HDD, DD);
  sgemm_kernel<<<dim3((KVHH*HDD)/64, TT/64), 256>>>(X, wv, nullptr, V, KVHH*HDD, DD);
  // 3. attention
  attn_kernel<<<dim3(SS/128, HH, BB), 128>>>();
  // 4. WO
  sgemm_kernel<<<dim3(DD/64, TT/64), 256>>>(ATT, wo, nullptr, AO, DD, DD);
  // 5. mix + residual (writes out_mixed and out_h)
  mix_kernel<<<dim3(DD/64, TT/64), 256>>>(hidden, prev, mixw, mixb, out_mixed, out_h);
  // 6. h2 = rmsnorm(h, ln2)
  rmsnorm_kernel<<<TT, 256>>>(out_h, ln2, H2);
  // 7. gating + routing
  zero_kernel<<<1, 32>>>();
  gate_kernel<<<TT/8, 256>>>(gatew);
  scan_kernel<<<1, 32>>>();
  scatter_kernel<<<TT/256, 256>>>();
  // 8. MoE expert GEMMs (grouped, sparse top-2)
  moe_up_kernel<<<dim3(FFF/64, TT/64, EE), 256>>>(w1, w3);
  moe_down_kernel<<<dim3(DD/64, TT/64, EE), 256>>>(w2);
  // 9. combine into h (deterministic; slots recorded per token)
  combine_kernel<<<TT, 256>>>(out_h);
  // 10. compression head
  sgemm_kernel<<<dim3(CCOMP/64, TT/64), 256>>>(out_h, compw, compb, out_comp, CCOMP, DD);
}

// round 3
// speedup vs baseline: 2.2846x; 2.2846x over previous
#include <cuda_runtime.h>
#include <math.h>
#include <stdint.h>

#define BB 4
#define SS 1024
#define DD 1024
#define TT (BB*SS)           // 4096 tokens
#define HH 16
#define KVHH 4
#define HDD 64
#define EE 8
#define FFF 2816
#define CCOMP 256
#define NSLOT (TT*2)         // 8192 (token, expert) slots

// ---------------- scratch (static device globals; no runtime alloc) ----------
__device__ float g_X[TT*DD];
__device__ float g_Q[TT*DD];
__device__ float g_K[TT*KVHH*HDD];
__device__ float g_V[TT*KVHH*HDD];
__device__ float g_attn[TT*DD];
__device__ float g_attnout[TT*DD];
__device__ float g_h2[TT*DD];
__device__ float g_act[NSLOT*FFF];      // h1 then silu(h1)*h3 (in-place)
__device__ float g_h3[NSLOT*FFF];
__device__ float g_part[NSLOT*DD];
__device__ int   g_tok[NSLOT];
__device__ float g_slotw[NSLOT];
__device__ int   g_tokslot[TT*2];
__device__ int   g_te[TT*2];
__device__ float g_tw[TT*2];
__device__ int   g_cnt[EE];
__device__ int   g_off[EE+1];
__device__ int   g_cur[EE];

// ---------------- tf32 helpers ----------------------------------------------
__device__ __forceinline__ uint32_t f2tf(float f) {
  uint32_t u;
  asm("cvt.rna.tf32.f32 %0, %1;" : "=r"(u) : "f"(f));
  return u;
}
__device__ __forceinline__ void mma_tf32(float c[4],
    uint32_t a0, uint32_t a1, uint32_t a2, uint32_t a3,
    uint32_t b0, uint32_t b1) {
  asm volatile(
    "mma.sync.aligned.m16n8k8.row.col.f32.tf32.tf32.f32 "
    "{%0,%1,%2,%3},{%4,%5,%6,%7},{%8,%9},{%0,%1,%2,%3};"
    : "+f"(c[0]), "+f"(c[1]), "+f"(c[2]), "+f"(c[3])
    : "r"(a0), "r"(a1), "r"(a2), "r"(a3), "r"(b0), "r"(b1));
}

// ---------------- unified TF32 tensor-core GEMM -------------------------------
// Block 128x128, 256 thr = 8 warps (2 warpM x 4 warpN), warp tile 64x32.
// K chunk 32/stage; smem k-major [32][136] (+8 pad => conflict-free frag LDS);
// register prefetch hides LDG under compute.
// MODE 0: C = A@B (+bias)            MODE 1: mix (A concat A2; C=mixed, C2=h)
// MODE 2: MoE up (gathered rows)     MODE 3: MoE down (slot rows, slotw scale)
template<int MODE>
__global__ __launch_bounds__(256) void gemm_tf32(
    const float* __restrict__ A, const float* __restrict__ A2,
    const float* __restrict__ B, const float* __restrict__ bias,
    const float* __restrict__ hidden, float* __restrict__ C,
    float* __restrict__ C2, int K, int N) {
  __shared__ uint32_t As[32][136];
  __shared__ uint32_t Bs[32][136];

  int base = 0, cnt = 0;
  if (MODE == 2 || MODE == 3) {
    int e = blockIdx.z;
    base = g_off[e];
    cnt = g_off[e+1] - base;
    if ((int)(blockIdx.y * 128) >= cnt) return;
    B += (size_t)e * K * N;
  }
  int rowBase = blockIdx.y * 128;
  int colBase = blockIdx.x * 128;
  int tid = threadIdx.x;
  int lane = tid & 31;
  int warp = tid >> 5;
  int warpM = warp & 1;
  int warpN = warp >> 1;

  int am = tid >> 1;            // fill row 0..127
  const float* arow0 = nullptr;
  const float* arow1 = nullptr;
  if (MODE == 0) {
    arow0 = A + (size_t)(rowBase + am) * K;
  } else if (MODE == 1) {
    arow0 = A  + (size_t)(rowBase + am) * DD;
    arow1 = A2 + (size_t)(rowBase + am) * DD;
  } else if (MODE == 2) {
    int rr = rowBase + am; if (rr > cnt - 1) rr = cnt - 1;
    arow0 = A + (size_t)g_tok[base + rr] * K;
  } else {
    int rr = rowBase + am; if (rr > cnt - 1) rr = cnt - 1;
    arow0 = A + (size_t)(base + rr) * K;
  }
  int acol = (tid & 1) * 16;

  int bk = tid >> 3;            // 0..31
  int bc = (tid & 7) * 4;
  const float* brow = B + (size_t)bk * N + colBase + bc;

  float4 pa[4], pb[4];
  auto ldA = [&](int k0) {
#pragma unroll
    for (int j = 0; j < 4; j++) {
      const float* p = arow0;
      int kk = k0 + acol + j * 4;
      if (MODE == 1 && kk >= DD) { p = arow1; kk -= DD; }
      pa[j] = *(const float4*)(p + kk);
    }
  };
  auto ldB = [&](int k0) {
#pragma unroll
    for (int j = 0; j < 4; j++)
      pb[j] = *(const float4*)(brow + (size_t)k0 * N + j * 32);
  };
  auto stA = [&]() {
#pragma unroll
    for (int j = 0; j < 4; j++) {
      int c = acol + j * 4;
      As[c  ][am] = f2tf(pa[j].x);
      As[c+1][am] = f2tf(pa[j].y);
      As[c+2][am] = f2tf(pa[j].z);
      As[c+3][am] = f2tf(pa[j].w);
    }
  };
  auto stB = [&]() {
#pragma unroll
    for (int j = 0; j < 4; j++) {
      int c = bc + j * 32;
      Bs[bk][c  ] = f2tf(pb[j].x);
      Bs[bk][c+1] = f2tf(pb[j].y);
      Bs[bk][c+2] = f2tf(pb[j].z);
      Bs[bk][c+3] = f2tf(pb[j].w);
    }
  };

  float acc[4][4][4] = {};
  int kq = lane & 3;
  int mq = lane >> 2;

  ldA(0); ldB(0);
  stA(); stB();
  __syncthreads();
  for (int k0 = 0; k0 < K; k0 += 32) {
    bool more = (k0 + 32) < K;
    if (more) { ldA(k0 + 32); ldB(k0 + 32); }
#pragma unroll
    for (int kc = 0; kc < 4; kc++) {
      int kb = kc * 8;
      uint32_t af[4][4];
#pragma unroll
      for (int mt = 0; mt < 4; mt++) {
        int mb = warpM * 64 + mt * 16 + mq;
        af[mt][0] = As[kb + kq    ][mb];
        af[mt][1] = As[kb + kq    ][mb + 8];
        af[mt][2] = As[kb + kq + 4][mb];
        af[mt][3] = As[kb + kq + 4][mb + 8];
      }
      uint32_t bf[4][2];
#pragma unroll
      for (int nt = 0; nt < 4; nt++) {
        int nb = warpN * 32 + nt * 8 + mq;
        bf[nt][0] = Bs[kb + kq    ][nb];
        bf[nt][1] = Bs[kb + kq + 4][nb];
      }
#pragma unroll
      for (int mt = 0; mt < 4; mt++)
#pragma unroll
        for (int nt = 0; nt < 4; nt++)
          mma_tf32(acc[mt][nt], af[mt][0], af[mt][1], af[mt][2], af[mt][3],
                   bf[nt][0], bf[nt][1]);
    }
    __syncthreads();
    if (more) { stA(); stB(); __syncthreads(); }
  }

#pragma unroll
  for (int mt = 0; mt < 4; mt++) {
#pragma unroll
    for (int half = 0; half < 2; half++) {
      int r = rowBase + warpM * 64 + mt * 16 + mq + half * 8;
#pragma unroll
      for (int nt = 0; nt < 4; nt++) {
        int n = colBase + warpN * 32 + nt * 8 + 2 * kq;
        float v0 = acc[mt][nt][half * 2];
        float v1 = acc[mt][nt][half * 2 + 1];
        if (MODE == 0) {
          if (bias) { v0 += bias[n]; v1 += bias[n + 1]; }
          *(float2*)(C + (size_t)r * N + n) = make_float2(v0, v1);
        } else if (MODE == 1) {
          v0 += bias[n]; v1 += bias[n + 1];
          *(float2*)(C + (size_t)r * N + n) = make_float2(v0, v1);
          float h0 = hidden[(size_t)r * N + n];
          float h1 = hidden[(size_t)r * N + n + 1];
          *(float2*)(C2 + (size_t)r * N + n) = make_float2(h0 + v0, h1 + v1);
        } else if (MODE == 2) {
          if (r < cnt)
            *(float2*)(C + (size_t)(base + r) * N + n) = make_float2(v0, v1);
        } else {
          if (r < cnt) {
            float w = g_slotw[base + r];
            *(float2*)(C + (size_t)(base + r) * N + n) =
                make_float2(w * v0, w * v1);
          }
        }
      }
    }
  }
}

// ---------------- rmsnorm ----------------------------------------------------
__global__ __launch_bounds__(256) void rmsnorm_kernel(
    const float* __restrict__ x, const float* __restrict__ w, float* __restrict__ out) {
  int row = blockIdx.x;
  const float* xr = x + (size_t)row * DD;
  float ss = 0.f;
  for (int i = threadIdx.x; i < DD; i += 256) { float v = xr[i]; ss += v * v; }
  __shared__ float red[8];
#pragma unroll
  for (int o = 16; o; o >>= 1) ss += __shfl_xor_sync(0xffffffffu, ss, o);
  if ((threadIdx.x & 31) == 0) red[threadIdx.x >> 5] = ss;
  __syncthreads();
  if (threadIdx.x < 8) {
    float v = red[threadIdx.x];
#pragma unroll
    for (int o = 4; o; o >>= 1) v += __shfl_xor_sync(0xffu, v, o);
    if (threadIdx.x == 0) red[0] = rsqrtf(v / (float)DD + 1e-6f);
  }
  __syncthreads();
  float r = red[0];
  for (int i = threadIdx.x; i < DD; i += 256) out[(size_t)row * DD + i] = w[i] * (xr[i] * r);
}

// ---------------- attention (flash-lite, no mask) ----------------------------
__global__ __launch_bounds__(128) void attn_kernel() {
  int q = blockIdx.x * 128 + threadIdx.x;
  int h = blockIdx.y;
  int b = blockIdx.z;
  int t = b * SS + q;
  int kv = h / (HH / KVHH);
  const float* qp = g_Q + (size_t)t * DD + h * HDD;
  float qr[HDD];
#pragma unroll
  for (int i = 0; i < HDD; i++) qr[i] = qp[i] * 0.125f;
  float acc[HDD] = {};
  float m = -1e30f, l = 0.f;
  __shared__ float Ks[32][HDD];
  __shared__ float Vs[32][HDD];
  int lr = threadIdx.x >> 2;
  int lc = (threadIdx.x & 3) * 16;
  for (int kt = 0; kt < SS; kt += 32) {
    const float* kp = g_K + (size_t)(b*SS + kt + lr) * (KVHH*HDD) + kv*HDD + lc;
    const float* vp = g_V + (size_t)(b*SS + kt + lr) * (KVHH*HDD) + kv*HDD + lc;
#pragma unroll
    for (int i = 0; i < 4; i++) {
      *(float4*)&Ks[lr][lc + i*4] = *(const float4*)(kp + i*4);
      *(float4*)&Vs[lr][lc + i*4] = *(const float4*)(vp + i*4);
    }
    __syncthreads();
    float sc[32];
#pragma unroll
    for (int j = 0; j < 32; j++) {
      float s = 0.f;
#pragma unroll
      for (int i = 0; i < HDD/4; i++) {
        float4 k4 = *(const float4*)&Ks[j][i*4];
        s += qr[i*4]*k4.x + qr[i*4+1]*k4.y + qr[i*4+2]*k4.z + qr[i*4+3]*k4.w;
      }
      sc[j] = s;
    }
    float mt = m;
#pragma unroll
    for (int j = 0; j < 32; j++) mt = fmaxf(mt, sc[j]);
    float corr = __expf(m - mt);
    m = mt;
    l *= corr;
#pragma unroll
    for (int i = 0; i < HDD; i++) acc[i] *= corr;
#pragma unroll
    for (int j = 0; j < 32; j++) {
      float p = __expf(sc[j] - m);
      l += p;
#pragma unroll
      for (int i = 0; i < HDD/4; i++) {
        float4 v4 = *(const float4*)&Vs[j][i*4];
        acc[i*4]   += p * v4.x;
        acc[i*4+1] += p * v4.y;
        acc[i*4+2] += p * v4.z;
        acc[i*4+3] += p * v4.w;
      }
    }
    __syncthreads();
  }
  float inv = 1.f / l;
  float* op = g_attn + (size_t)t * DD + h * HDD;
#pragma unroll
  for (int i = 0; i < HDD; i++) op[i] = acc[i] * inv;
}

// ---------------- MoE routing ------------------------------------------------
__global__ void zero_kernel() { if (threadIdx.x < EE) g_cnt[threadIdx.x] = 0; }

__global__ __launch_bounds__(256) void gate_kernel(const float* __restrict__ gw) {
  int warp = (blockIdx.x * 256 + threadIdx.x) >> 5;
  int lane = threadIdx.x & 31;
  if (warp >= TT) return;
  const float* x = g_h2 + (size_t)warp * DD;
  float acc[EE] = {};
  for (int k = lane; k < DD; k += 32) {
    float xv = x[k];
    const float* g = gw + (size_t)k * EE;
#pragma unroll
    for (int e = 0; e < EE; e++) acc[e] += xv * g[e];
  }
#pragma unroll
  for (int e = 0; e < EE; e++)
#pragma unroll
    for (int o = 16; o; o >>= 1) acc[e] += __shfl_xor_sync(0xffffffffu, acc[e], o);
  if (lane == 0) {
    float mx = acc[0];
#pragma unroll
    for (int e = 1; e < EE; e++) mx = fmaxf(mx, acc[e]);
    float p[EE];
#pragma unroll
    for (int e = 0; e < EE; e++) p[e] = __expf(acc[e] - mx);
    int i0 = 0;
#pragma unroll
    for (int e = 1; e < EE; e++) if (p[e] > p[i0]) i0 = e;
    int i1 = (i0 == 0) ? 1 : 0;
#pragma unroll
    for (int e = 0; e < EE; e++) if (e != i0 && p[e] > p[i1]) i1 = e;
    float w0 = p[i0], w1 = p[i1];
    float inv = 1.f / (w0 + w1);
    w0 *= inv; w1 *= inv;
    g_te[warp*2] = i0; g_te[warp*2+1] = i1;
    g_tw[warp*2] = w0; g_tw[warp*2+1] = w1;
    atomicAdd(&g_cnt[i0], 1);
    atomicAdd(&g_cnt[i1], 1);
  }
}

__global__ void scan_kernel() {
  if (threadIdx.x == 0) {
    int o = 0;
    for (int e = 0; e < EE; e++) { g_off[e] = o; o += g_cnt[e]; g_cur[e] = 0; }
    g_off[EE] = o;
  }
}

__global__ __launch_bounds__(256) void scatter_kernel() {
  int t = blockIdx.x * 256 + threadIdx.x;
  if (t >= TT) return;
#pragma unroll
  for (int k = 0; k < 2; k++) {
    int e = g_te[t*2+k];
    int pos = atomicAdd(&g_cur[e], 1);
    int slot = g_off[e] + pos;
    g_tok[slot] = t;
    g_slotw[slot] = g_tw[t*2+k];
    g_tokslot[t*2+k] = slot;
  }
}

// ---------------- activation: g_act = silu(g_act) * g_h3 (in-place) ----------
__global__ __launch_bounds__(256) void act_kernel() {
  size_t i = ((size_t)blockIdx.x * 256 + threadIdx.x) * 4;
  float4 h1 = *(float4*)(g_act + i);
  float4 h3 = *(const float4*)(g_h3 + i);
  h1.x = h1.x / (1.f + __expf(-h1.x)) * h3.x;
  h1.y = h1.y / (1.f + __expf(-h1.y)) * h3.y;
  h1.z = h1.z / (1.f + __expf(-h1.z)) * h3.z;
  h1.w = h1.w / (1.f + __expf(-h1.w)) * h3.w;
  *(float4*)(g_act + i) = h1;
}

// ---------------- combine: h += part[slot0] + part[slot1] --------------------
__global__ __launch_bounds__(256) void combine_kernel(float* __restrict__ outh) {
  int t = blockIdx.x;
  int s0 = g_tokslot[t*2], s1 = g_tokslot[t*2+1];
  int i = threadIdx.x * 4;
  float4 h  = *(float4*)(outh + (size_t)t * DD + i);
  float4 p0 = *(const float4*)(g_part + (size_t)s0 * DD + i);
  float4 p1 = *(const float4*)(g_part + (size_t)s1 * DD + i);
  h.x += p0.x + p1.x; h.y += p0.y + p1.y; h.z += p0.z + p1.z; h.w += p0.w + p1.w;
  *(float4*)(outh + (size_t)t * DD + i) = h;
}

// ---------------- launcher ---------------------------------------------------
extern "C" void kernel_launch(void* const* d_in, const int* in_sizes, int n_in,
                              void* d_out, int out_size) {
  const float* hidden = (const float*)d_in[0];
  const float* prev   = (const float*)d_in[2];
  const float* wq     = (const float*)d_in[3];
  const float* wk     = (const float*)d_in[4];
  const float* wv     = (const float*)d_in[5];
  const float* wo     = (const float*)d_in[6];
  const float* mixw   = (const float*)d_in[7];
  const float* mixb   = (const float*)d_in[8];
  const float* gatew  = (const float*)d_in[9];
  const float* w1     = (const float*)d_in[10];
  const float* w2     = (const float*)d_in[11];
  const float* w3     = (const float*)d_in[12];
  const float* ln1    = (const float*)d_in[13];
  const float* ln2    = (const float*)d_in[14];
  const float* compw  = (const float*)d_in[15];
  const float* compb  = (const float*)d_in[16];

  float* out_h     = (float*)d_out;
  float* out_mixed = out_h + (size_t)TT * DD;
  float* out_comp  = out_mixed + (size_t)TT * DD;

  void *pX, *pQ, *pK, *pV, *pAttn, *pAO, *pH2, *pAct, *pH3, *pPart;
  cudaGetSymbolAddress(&pX, g_X);
  cudaGetSymbolAddress(&pQ, g_Q);
  cudaGetSymbolAddress(&pK, g_K);
  cudaGetSymbolAddress(&pV, g_V);
  cudaGetSymbolAddress(&pAttn, g_attn);
  cudaGetSymbolAddress(&pAO, g_attnout);
  cudaGetSymbolAddress(&pH2, g_h2);
  cudaGetSymbolAddress(&pAct, g_act);
  cudaGetSymbolAddress(&pH3, g_h3);
  cudaGetSymbolAddress(&pPart, g_part);
  float* X = (float*)pX; float* Q = (float*)pQ; float* K = (float*)pK;
  float* V = (float*)pV; float* ATT = (float*)pAttn; float* AO = (float*)pAO;
  float* H2 = (float*)pH2; float* ACT = (float*)pAct; float* H3 = (float*)pH3;
  float* PART = (float*)pPart;

  rmsnorm_kernel<<<TT, 256>>>(hidden, ln1, X);
  gemm_tf32<0><<<dim3(DD/128, TT/128), 256>>>(X, nullptr, wq, nullptr, nullptr, Q, nullptr, DD, DD);
  gemm_tf32<0><<<dim3((KVHH*HDD)/128, TT/128), 256>>>(X, nullptr, wk, nullptr, nullptr, K, nullptr, DD, KVHH*HDD);
  gemm_tf32<0><<<dim3((KVHH*HDD)/128, TT/128), 256>>>(X, nullptr, wv, nullptr, nullptr, V, nullptr, DD, KVHH*HDD);
  attn_kernel<<<dim3(SS/128, HH, BB), 128>>>();
  gemm_tf32<0><<<dim3(DD/128, TT/128), 256>>>(ATT, nullptr, wo, nullptr, nullptr, AO, nullptr, DD, DD);
  gemm_tf32<1><<<dim3(DD/128, TT/128), 256>>>(AO, prev, mixw, mixb, hidden, out_mixed, out_h, 2*DD, DD);
  rmsnorm_kernel<<<TT, 256>>>(out_h, ln2, H2);
  zero_kernel<<<1, 32>>>();
  gate_kernel<<<TT/8, 256>>>(gatew);
  scan_kernel<<<1, 32>>>();
  scatter_kernel<<<TT/256, 256>>>();
  gemm_tf32<2><<<dim3(FFF/128, TT/128, EE), 256>>>(H2, nullptr, w1, nullptr, nullptr, ACT, nullptr, DD, FFF);
  gemm_tf32<2><<<dim3(FFF/128, TT/128, EE), 256>>>(H2, nullptr, w3, nullptr, nullptr, H3, nullptr, DD, FFF);
  act_kernel<<<(int)(((size_t)NSLOT*FFF)/(256*4)), 256>>>();
  gemm_tf32<3><<<dim3(DD/128, TT/128, EE), 256>>>(ACT, nullptr, w2, nullptr, nullptr, PART, nullptr, FFF, DD);
  combine_kernel<<<TT, 256>>>(out_h);
  gemm_tf32<0><<<dim3(CCOMP/128, TT/128), 256>>>(out_h, nullptr, compw, compb, nullptr, out_comp, nullptr, DD, CCOMP);
}